// round 16
// baseline (speedup 1.0000x reference)
#include <cuda_runtime.h>
#include <cuda_fp16.h>

#define N_NODES 100000
#define N_EDGES 1600000
#define F 64
#define NUM_GRAPHS 64
#define TOPO_DIM 16
#define NUM_CLASSES 4

#define SCAN_BLK 512
#define SCAN_NBLK ((N_NODES + SCAN_BLK - 1) / SCAN_BLK)   // 196

#define SA 72            // smem row stride (halfs) — conflict-free for frag loads
#define BIN_BLOCKS 1563  // ceil(N_EDGES/8 / 128)
#define G1_BLOCKS 1563   // ceil(N_NODES / 64)

// Scratch (device globals; allocation-free per harness rules)
__device__ int      g_cnt[N_NODES];       // zeroed at load + by k_scan each run
__device__ int      g_total;              // zeroed by k_pre each run
__device__ int      g_rowptr[N_NODES];
__device__ int      g_fill[N_NODES];
__device__ int      g_srcs[N_EDGES];
__device__ float    g_dis[N_NODES];
__device__ __half   g_bufA[N_NODES * F];   // xs1 (fp16) — layer-1 gathered buffer
__device__ __half   g_bufH[N_NODES * F];   // xs2 (fp16) — layer-2 gathered buffer
__device__ __half   g_W1t[F * F];          // W1 transposed fp16 [n][k]
__device__ __half   g_W2t[F * F];          // W2 transposed fp16 [n][k]
__device__ float    g_gsum[NUM_GRAPHS * F];
__device__ float    g_gcnt[NUM_GRAPHS];

// ---------------- pre: degree histogram (8 edges/thr) + zero misc + prepW ----
__global__ void k_pre(const int* __restrict__ edge,
                      const float* __restrict__ W1, const float* __restrict__ W2) {
    int t = blockIdx.x * blockDim.x + threadIdx.x;
    if (t == 0) g_total = 0;
    if (t < NUM_GRAPHS * F) g_gsum[t] = 0.0f;
    if (t < NUM_GRAPHS) g_gcnt[t] = 0.0f;
    if (t >= 4096 && t < 8192) {           // weight transpose + fp16
        int e = t - 4096;
        int k = e >> 6, n = e & 63;
        g_W1t[n * F + k] = __float2half(W1[e]);
        g_W2t[n * F + k] = __float2half(W2[e]);
    }
    if (t < N_EDGES / 8) {
        const int4* D = (const int4*)(edge + N_EDGES);
        int4 d0 = D[2 * t];
        int4 d1 = D[2 * t + 1];
        atomicAdd(&g_cnt[d0.x], 1);
        atomicAdd(&g_cnt[d0.y], 1);
        atomicAdd(&g_cnt[d0.z], 1);
        atomicAdd(&g_cnt[d0.w], 1);
        atomicAdd(&g_cnt[d1.x], 1);
        atomicAdd(&g_cnt[d1.y], 1);
        atomicAdd(&g_cnt[d1.z], 1);
        atomicAdd(&g_cnt[d1.w], 1);
    }
}

// ---------------- single-kernel scan (atomic block base) + dis + gcnt --------
__global__ void k_scan(const int* __restrict__ batch) {
    __shared__ int s[SCAN_BLK];
    __shared__ int s_base;
    int t = threadIdx.x;
    int i = blockIdx.x * SCAN_BLK + t;
    int v = (i < N_NODES) ? g_cnt[i] : 0;
    if (i < N_NODES) {
        g_dis[i] = rsqrtf((float)v + 1.0f);
        int g = batch[i];
        unsigned active = __activemask();
        unsigned mask = __match_any_sync(active, g);
        int leader = __ffs(mask) - 1;
        if ((t & 31) == leader)
            atomicAdd(&g_gcnt[g], (float)__popc(mask));
    }
    s[t] = v;
    __syncthreads();
    #pragma unroll
    for (int off = 1; off < SCAN_BLK; off <<= 1) {
        int add = (t >= off) ? s[t - off] : 0;
        __syncthreads();
        s[t] += add;
        __syncthreads();
    }
    if (t == SCAN_BLK - 1) s_base = atomicAdd(&g_total, s[SCAN_BLK - 1]);
    __syncthreads();
    if (i < N_NODES) {
        int rp = s_base + s[t] - v;
        g_rowptr[i] = rp;
        g_fill[i] = rp;
        g_cnt[i] = 0;      // clean histogram for next graph replay
    }
}

// ---------------- helpers ----------------
__device__ __forceinline__ void acc_half8(float* acc, uint4 u) {
    float2 f;
    f = __half22float2(*(__half2*)&u.x); acc[0] += f.x; acc[1] += f.y;
    f = __half22float2(*(__half2*)&u.y); acc[2] += f.x; acc[3] += f.y;
    f = __half22float2(*(__half2*)&u.z); acc[4] += f.x; acc[5] += f.y;
    f = __half22float2(*(__half2*)&u.w); acc[6] += f.x; acc[7] += f.y;
}

__device__ __forceinline__ void hacc4(__half2* hs, uint4 u) {
    hs[0] = __hadd2(hs[0], *(__half2*)&u.x);
    hs[1] = __hadd2(hs[1], *(__half2*)&u.y);
    hs[2] = __hadd2(hs[2], *(__half2*)&u.z);
    hs[3] = __hadd2(hs[3], *(__half2*)&u.w);
}

// CSR gather-sum from `buf`: fp16 HADD2 accumulation in 8-edge windows.
__device__ __forceinline__ void gather_sum(float* acc, int beg, int end, int lane,
                                           const __half* buf) {
    const uint4* A = (const uint4*)buf;
    int i = beg;
    while (i < end) {
        __half2 hs[4];
        hs[0] = hs[1] = hs[2] = hs[3] = __float2half2_rn(0.0f);
        if (end - i >= 8) {
            int s[8];
            #pragma unroll
            for (int j = 0; j < 8; j++) s[j] = __ldg(&g_srcs[i + j]);
            uint4 u[8];
            #pragma unroll
            for (int j = 0; j < 8; j++) u[j] = __ldg(&A[s[j] * 8 + lane]);
            #pragma unroll
            for (int j = 0; j < 8; j++) hacc4(hs, u[j]);
            i += 8;
        } else {
            for (; i < end; i++) {
                int s = __ldg(&g_srcs[i]);
                hacc4(hs, __ldg(&A[s * 8 + lane]));
            }
        }
        float2 f;
        f = __half22float2(hs[0]); acc[0] += f.x; acc[1] += f.y;
        f = __half22float2(hs[1]); acc[2] += f.x; acc[3] += f.y;
        f = __half22float2(hs[2]); acc[4] += f.x; acc[5] += f.y;
        f = __half22float2(hs[3]); acc[6] += f.x; acc[7] += f.y;
    }
}

__device__ __forceinline__ void red_v4(float* p, float a, float b, float c, float d) {
    unsigned long long ga;
    asm("cvta.to.global.u64 %0, %1;" : "=l"(ga) : "l"(p));
    asm volatile("red.global.add.v4.f32 [%0], {%1,%2,%3,%4};"
                 :: "l"(ga), "f"(a), "f"(b), "f"(c), "f"(d) : "memory");
}

__device__ __forceinline__ void mma16816(float* c,
    unsigned a0, unsigned a1, unsigned a2, unsigned a3,
    unsigned b0, unsigned b1) {
    asm volatile("mma.sync.aligned.m16n8k16.row.col.f32.f16.f16.f32 "
        "{%0,%1,%2,%3}, {%4,%5,%6,%7}, {%8,%9}, {%0,%1,%2,%3};"
        : "+f"(c[0]), "+f"(c[1]), "+f"(c[2]), "+f"(c[3])
        : "r"(a0), "r"(a1), "r"(a2), "r"(a3), "r"(b0), "r"(b1));
}

// mma mainloop + epilogue over 64 rows; MUST be run by threads 0..127 (4 warps).
// Output goes to `outbuf` (scaled by dis, fp16).
__device__ __forceinline__ void mma_body(const __half* As, const __half* Wt, int base,
                                         __half* outbuf) {
    int lane = threadIdx.x & 31;
    int w = threadIdx.x >> 5;
    int g = lane >> 2, tg = lane & 3;
    int R = w * 16;
    float c[8][4] = {};
    #pragma unroll
    for (int k0 = 0; k0 < F; k0 += 16) {
        unsigned a0 = *(const unsigned*)&As[(R + g) * SA + k0 + tg * 2];
        unsigned a1 = *(const unsigned*)&As[(R + g + 8) * SA + k0 + tg * 2];
        unsigned a2 = *(const unsigned*)&As[(R + g) * SA + k0 + tg * 2 + 8];
        unsigned a3 = *(const unsigned*)&As[(R + g + 8) * SA + k0 + tg * 2 + 8];
        #pragma unroll
        for (int n = 0; n < 8; n++) {
            unsigned b0 = *(const unsigned*)&Wt[(n * 8 + g) * SA + k0 + tg * 2];
            unsigned b1 = *(const unsigned*)&Wt[(n * 8 + g) * SA + k0 + tg * 2 + 8];
            mma16816(c[n], a0, a1, a2, a3, b0, b1);
        }
    }
    int row0 = base + R + g;
    int row1 = row0 + 8;
    float dis0 = (row0 < N_NODES) ? g_dis[row0] : 0.0f;
    float dis1 = (row1 < N_NODES) ? g_dis[row1] : 0.0f;
    #pragma unroll
    for (int n = 0; n < 8; n++) {
        int col = n * 8 + tg * 2;
        if (row0 < N_NODES) {
            __half2 h = __floats2half2_rn(c[n][0] * dis0, c[n][1] * dis0);
            *(__half2*)&outbuf[row0 * F + col] = h;
        }
        if (row1 < N_NODES) {
            __half2 h = __floats2half2_rn(c[n][2] * dis1, c[n][3] * dis1);
            *(__half2*)&outbuf[row1 * F + col] = h;
        }
    }
}

// Load transposed weights into SA-strided smem. `nthreads` participating.
template<int NT>
__device__ __forceinline__ void load_Wt_smem(__half* Wt, const __half* Wg) {
    int t = threadIdx.x;
    #pragma unroll
    for (int j = 0; j < 512 / NT; j++) {
        int idx = t + NT * j;          // 512 uint4
        int n = idx >> 3, q = idx & 7;
        uint4 u = ((const uint4*)Wg)[idx];
        __half* p = &Wt[n * SA + q * 8];
        *(unsigned*)(p + 0) = u.x;
        *(unsigned*)(p + 2) = u.y;
        *(unsigned*)(p + 4) = u.z;
        *(unsigned*)(p + 6) = u.w;
    }
}

// ---------------- fused: bin (latency-bound) ∪ GEMM1 (DRAM/tensor-bound) -----
__global__ void k_binmm1(const int* __restrict__ edge, const float* __restrict__ x) {
    __shared__ __half As[64 * SA];
    __shared__ __half Wt[64 * SA];
    if (blockIdx.x < BIN_BLOCKS) {
        int t = blockIdx.x * 128 + threadIdx.x;
        if (t < N_EDGES / 8) {
            const int4* S = (const int4*)edge;
            const int4* D = (const int4*)(edge + N_EDGES);
            int4 s0 = S[2 * t], s1 = S[2 * t + 1];
            int4 d0 = D[2 * t], d1 = D[2 * t + 1];
            int p0 = atomicAdd(&g_fill[d0.x], 1);
            int p1 = atomicAdd(&g_fill[d0.y], 1);
            int p2 = atomicAdd(&g_fill[d0.z], 1);
            int p3 = atomicAdd(&g_fill[d0.w], 1);
            int p4 = atomicAdd(&g_fill[d1.x], 1);
            int p5 = atomicAdd(&g_fill[d1.y], 1);
            int p6 = atomicAdd(&g_fill[d1.z], 1);
            int p7 = atomicAdd(&g_fill[d1.w], 1);
            g_srcs[p0] = s0.x;
            g_srcs[p1] = s0.y;
            g_srcs[p2] = s0.z;
            g_srcs[p3] = s0.w;
            g_srcs[p4] = s1.x;
            g_srcs[p5] = s1.y;
            g_srcs[p6] = s1.z;
            g_srcs[p7] = s1.w;
        }
    } else {
        int t = threadIdx.x;
        int base = (blockIdx.x - BIN_BLOCKS) * 64;
        load_Wt_smem<128>(Wt, g_W1t);
        #pragma unroll
        for (int j = 0; j < 8; j++) {
            int idx = t + 128 * j;          // 1024 float4
            int r = idx >> 4, q = idx & 15;
            int row = base + r;
            float4 f = (row < N_NODES) ? ((const float4*)x)[(long long)row * 16 + q]
                                       : make_float4(0.f, 0.f, 0.f, 0.f);
            __half* p = &As[r * SA + q * 4];
            *(__half2*)(p + 0) = __floats2half2_rn(f.x, f.y);
            *(__half2*)(p + 2) = __floats2half2_rn(f.z, f.w);
        }
        __syncthreads();
        mma_body(As, Wt, base, g_bufA);
    }
}

// ---------------- fused agg0 + GEMM2: 512 threads, 64 nodes/block ------------
// Phase 1 (all 512 threads): gather layer-1 sums from bufA, apply self-loop +
// bias + relu, write h (fp16) into SA-strided smem tile.
// Phase 2 (warps 0-3): HMMA h @ W2t, scale by dis, write xs2 to bufH.
// No race: reads bufA, writes bufH.
__global__ __launch_bounds__(512, 2) void k_agg0mm2(const float* __restrict__ b1) {
    __shared__ __half Hs[64 * SA];
    __shared__ __half Wt[64 * SA];
    int tid = threadIdx.x;
    int base = blockIdx.x * 64;
    load_Wt_smem<512>(Wt, g_W2t);
    int r = tid >> 3;                 // local node 0..63
    int lane = tid & 7;
    int node = base + r;
    float h[8] = {};
    if (node < N_NODES) {
        int beg = g_rowptr[node];
        int end = g_fill[node];
        float acc[8] = {};
        gather_sum(acc, beg, end, lane, g_bufA);
        float dis = g_dis[node];
        float xs[8] = {};
        acc_half8(xs, __ldg(&((const uint4*)g_bufA)[node * 8 + lane]));
        #pragma unroll
        for (int j = 0; j < 8; j++)
            h[j] = fmaxf(dis * (acc[j] + xs[j]) + b1[lane * 8 + j], 0.0f);
    }
    __half* p = &Hs[r * SA + lane * 8];
    #pragma unroll
    for (int j = 0; j < 4; j++)
        *(__half2*)(p + 2 * j) = __floats2half2_rn(h[2 * j], h[2 * j + 1]);
    __syncthreads();
    if (tid < 128) mma_body(Hs, Wt, base, g_bufH);
}

// ---------------- agg1 (reads bufH) fused with relu + mean-pool ----------------
__global__ void k_agg1(const float* __restrict__ b2, const int* __restrict__ batch) {
    __shared__ float hacc[32 * F];
    int tid = threadIdx.x;
    int s = tid >> 3;
    int lane = tid & 7;
    int base = blockIdx.x * 32;
    int node = base + s;
    int beg = g_rowptr[node];
    int end = g_fill[node];
    float acc[8] = {};
    gather_sum(acc, beg, end, lane, g_bufH);
    float dis = g_dis[node];
    float xs[8] = {};
    acc_half8(xs, __ldg(&((const uint4*)g_bufH)[node * 8 + lane]));
    float h[8];
    #pragma unroll
    for (int j = 0; j < 8; j++)
        h[j] = fmaxf(dis * (acc[j] + xs[j]) + b2[lane * 8 + j], 0.0f);
    #pragma unroll
    for (int j = 0; j < 8; j++) hacc[s * F + lane * 8 + j] = h[j];
    __syncthreads();

    int g0 = batch[base];
    int g1 = batch[base + 31];
    if (g0 == g1) {
        #pragma unroll
        for (int off = 16; off >= 1; off >>= 1) {
            if (s < off) {
                #pragma unroll
                for (int j = 0; j < 8; j++)
                    hacc[s * F + lane * 8 + j] += hacc[(s + off) * F + lane * 8 + j];
            }
            __syncthreads();
        }
        if (tid < 16) {
            float4 v = ((float4*)hacc)[tid];
            red_v4(&g_gsum[g0 * F + tid * 4], v.x, v.y, v.z, v.w);
        }
    } else {
        int g = batch[node];
        red_v4(&g_gsum[g * F + lane * 8 + 0], h[0], h[1], h[2], h[3]);
        red_v4(&g_gsum[g * F + lane * 8 + 4], h[4], h[5], h[6], h[7]);
    }
}

// ---------------- head ----------------
__global__ void k_head(const float* __restrict__ topo, const float* __restrict__ Wlin,
                       const float* __restrict__ blin, float* __restrict__ out) {
    int t = threadIdx.x;
    int g = t >> 2, c = t & 3;
    float inv = 1.0f / fmaxf(g_gcnt[g], 1.0f);
    float acc = blin[c];
    #pragma unroll
    for (int k = 0; k < F; k++)
        acc = fmaf(g_gsum[g * F + k] * inv, Wlin[k * NUM_CLASSES + c], acc);
    #pragma unroll
    for (int k = 0; k < TOPO_DIM; k++)
        acc = fmaf(topo[g * TOPO_DIM + k], Wlin[(F + k) * NUM_CLASSES + c], acc);
    out[g * NUM_CLASSES + c] = acc;
}

extern "C" void kernel_launch(void* const* d_in, const int* in_sizes, int n_in,
                              void* d_out, int out_size) {
    const float* x    = (const float*)d_in[0];
    const int*   edge = (const int*)d_in[1];
    const int*   batch= (const int*)d_in[2];
    const float* topo = (const float*)d_in[3];
    const float* W1   = (const float*)d_in[4];
    const float* b1   = (const float*)d_in[5];
    const float* W2   = (const float*)d_in[6];
    const float* b2   = (const float*)d_in[7];
    const float* Wlin = (const float*)d_in[8];
    const float* blin = (const float*)d_in[9];
    float* out = (float*)d_out;

    const int a1blocks = (N_NODES + 31) / 32;         // 3125
    const int fblocks = (N_NODES + 63) / 64;          // 1563
    const int eblocks = (N_EDGES / 8 + 255) / 256;    // 782

    k_pre<<<eblocks, 256>>>(edge, W1, W2);
    k_scan<<<SCAN_NBLK, SCAN_BLK>>>(batch);
    k_binmm1<<<BIN_BLOCKS + G1_BLOCKS, 128>>>(edge, x);
    k_agg0mm2<<<fblocks, 512>>>(b1);
    k_agg1<<<a1blocks, 256>>>(b2, batch);
    k_head<<<1, 256>>>(topo, Wlin, blin, out);
}

// round 17
// speedup vs baseline: 1.0200x; 1.0200x over previous
#include <cuda_runtime.h>
#include <cuda_fp16.h>

#define N_NODES 100000
#define N_EDGES 1600000
#define F 64
#define NUM_GRAPHS 64
#define TOPO_DIM 16
#define NUM_CLASSES 4

#define SCAN_BLK 512
#define SCAN_NBLK ((N_NODES + SCAN_BLK - 1) / SCAN_BLK)   // 196

#define SA 72            // smem row stride (halfs) — conflict-free for frag loads
#define BIN_BLOCKS 1563  // ceil(N_EDGES/8 / 128)
#define G1_BLOCKS 1563   // ceil(N_NODES / 64)

// Scratch (device globals; allocation-free per harness rules)
__device__ int      g_cnt[N_NODES];       // zeroed at load + by k_scan each run
__device__ int      g_total;              // zeroed by k_pre each run
__device__ int      g_rowptr[N_NODES];
__device__ int      g_fill[N_NODES];
__device__ int      g_srcs[N_EDGES];
__device__ float    g_dis[N_NODES];
__device__ __half   g_bufA[N_NODES * F];   // xs1 (fp16) — layer-1 gathered buffer
__device__ __half   g_bufH[N_NODES * F];   // xs2 (fp16) — layer-2 gathered buffer
__device__ __half   g_W1t[F * F];          // W1 transposed fp16 [n][k]
__device__ __half   g_W2t[F * F];          // W2 transposed fp16 [n][k]
__device__ float    g_gsum[NUM_GRAPHS * F];
__device__ float    g_gcnt[NUM_GRAPHS];

// ---------------- pre: degree histogram (8 edges/thr) + zero misc + prepW ----
__global__ void k_pre(const int* __restrict__ edge,
                      const float* __restrict__ W1, const float* __restrict__ W2) {
    int t = blockIdx.x * blockDim.x + threadIdx.x;
    if (t == 0) g_total = 0;
    if (t < NUM_GRAPHS * F) g_gsum[t] = 0.0f;
    if (t < NUM_GRAPHS) g_gcnt[t] = 0.0f;
    if (t >= 4096 && t < 8192) {           // weight transpose + fp16
        int e = t - 4096;
        int k = e >> 6, n = e & 63;
        g_W1t[n * F + k] = __float2half(W1[e]);
        g_W2t[n * F + k] = __float2half(W2[e]);
    }
    if (t < N_EDGES / 8) {
        const int4* D = (const int4*)(edge + N_EDGES);
        int4 d0 = D[2 * t];
        int4 d1 = D[2 * t + 1];
        atomicAdd(&g_cnt[d0.x], 1);
        atomicAdd(&g_cnt[d0.y], 1);
        atomicAdd(&g_cnt[d0.z], 1);
        atomicAdd(&g_cnt[d0.w], 1);
        atomicAdd(&g_cnt[d1.x], 1);
        atomicAdd(&g_cnt[d1.y], 1);
        atomicAdd(&g_cnt[d1.z], 1);
        atomicAdd(&g_cnt[d1.w], 1);
    }
}

// ---------------- single-kernel scan (atomic block base) + dis + gcnt --------
__global__ void k_scan(const int* __restrict__ batch) {
    __shared__ int s[SCAN_BLK];
    __shared__ int s_base;
    int t = threadIdx.x;
    int i = blockIdx.x * SCAN_BLK + t;
    int v = (i < N_NODES) ? g_cnt[i] : 0;
    if (i < N_NODES) {
        g_dis[i] = rsqrtf((float)v + 1.0f);
        int g = batch[i];
        unsigned active = __activemask();
        unsigned mask = __match_any_sync(active, g);
        int leader = __ffs(mask) - 1;
        if ((t & 31) == leader)
            atomicAdd(&g_gcnt[g], (float)__popc(mask));
    }
    s[t] = v;
    __syncthreads();
    #pragma unroll
    for (int off = 1; off < SCAN_BLK; off <<= 1) {
        int add = (t >= off) ? s[t - off] : 0;
        __syncthreads();
        s[t] += add;
        __syncthreads();
    }
    if (t == SCAN_BLK - 1) s_base = atomicAdd(&g_total, s[SCAN_BLK - 1]);
    __syncthreads();
    if (i < N_NODES) {
        int rp = s_base + s[t] - v;
        g_rowptr[i] = rp;
        g_fill[i] = rp;
        g_cnt[i] = 0;      // clean histogram for next graph replay
    }
}

// ---------------- helpers ----------------
__device__ __forceinline__ void acc_half8(float* acc, uint4 u) {
    float2 f;
    f = __half22float2(*(__half2*)&u.x); acc[0] += f.x; acc[1] += f.y;
    f = __half22float2(*(__half2*)&u.y); acc[2] += f.x; acc[3] += f.y;
    f = __half22float2(*(__half2*)&u.z); acc[4] += f.x; acc[5] += f.y;
    f = __half22float2(*(__half2*)&u.w); acc[6] += f.x; acc[7] += f.y;
}

__device__ __forceinline__ void hacc4(__half2* hs, uint4 u) {
    hs[0] = __hadd2(hs[0], *(__half2*)&u.x);
    hs[1] = __hadd2(hs[1], *(__half2*)&u.y);
    hs[2] = __hadd2(hs[2], *(__half2*)&u.z);
    hs[3] = __hadd2(hs[3], *(__half2*)&u.w);
}

// CSR gather-sum from `buf`: fp16 HADD2 accumulation in 8-edge windows.
__device__ __forceinline__ void gather_sum(float* acc, int beg, int end, int lane,
                                           const __half* buf) {
    const uint4* A = (const uint4*)buf;
    int i = beg;
    while (i < end) {
        __half2 hs[4];
        hs[0] = hs[1] = hs[2] = hs[3] = __float2half2_rn(0.0f);
        if (end - i >= 8) {
            int s[8];
            #pragma unroll
            for (int j = 0; j < 8; j++) s[j] = __ldg(&g_srcs[i + j]);
            uint4 u[8];
            #pragma unroll
            for (int j = 0; j < 8; j++) u[j] = __ldg(&A[s[j] * 8 + lane]);
            #pragma unroll
            for (int j = 0; j < 8; j++) hacc4(hs, u[j]);
            i += 8;
        } else {
            for (; i < end; i++) {
                int s = __ldg(&g_srcs[i]);
                hacc4(hs, __ldg(&A[s * 8 + lane]));
            }
        }
        float2 f;
        f = __half22float2(hs[0]); acc[0] += f.x; acc[1] += f.y;
        f = __half22float2(hs[1]); acc[2] += f.x; acc[3] += f.y;
        f = __half22float2(hs[2]); acc[4] += f.x; acc[5] += f.y;
        f = __half22float2(hs[3]); acc[6] += f.x; acc[7] += f.y;
    }
}

__device__ __forceinline__ void red_v4(float* p, float a, float b, float c, float d) {
    unsigned long long ga;
    asm("cvta.to.global.u64 %0, %1;" : "=l"(ga) : "l"(p));
    asm volatile("red.global.add.v4.f32 [%0], {%1,%2,%3,%4};"
                 :: "l"(ga), "f"(a), "f"(b), "f"(c), "f"(d) : "memory");
}

__device__ __forceinline__ void mma16816(float* c,
    unsigned a0, unsigned a1, unsigned a2, unsigned a3,
    unsigned b0, unsigned b1) {
    asm volatile("mma.sync.aligned.m16n8k16.row.col.f32.f16.f16.f32 "
        "{%0,%1,%2,%3}, {%4,%5,%6,%7}, {%8,%9}, {%0,%1,%2,%3};"
        : "+f"(c[0]), "+f"(c[1]), "+f"(c[2]), "+f"(c[3])
        : "r"(a0), "r"(a1), "r"(a2), "r"(a3), "r"(b0), "r"(b1));
}

// mma mainloop + epilogue over NROWS rows; run by threads 0..(NROWS*2-1)
// (NROWS/16 warps, warp w handles rows w*16..w*16+15).
template<int NROWS>
__device__ __forceinline__ void mma_body(const __half* As, const __half* Wt, int base,
                                         __half* outbuf) {
    int lane = threadIdx.x & 31;
    int w = threadIdx.x >> 5;
    int g = lane >> 2, tg = lane & 3;
    int R = w * 16;
    float c[8][4] = {};
    #pragma unroll
    for (int k0 = 0; k0 < F; k0 += 16) {
        unsigned a0 = *(const unsigned*)&As[(R + g) * SA + k0 + tg * 2];
        unsigned a1 = *(const unsigned*)&As[(R + g + 8) * SA + k0 + tg * 2];
        unsigned a2 = *(const unsigned*)&As[(R + g) * SA + k0 + tg * 2 + 8];
        unsigned a3 = *(const unsigned*)&As[(R + g + 8) * SA + k0 + tg * 2 + 8];
        #pragma unroll
        for (int n = 0; n < 8; n++) {
            unsigned b0 = *(const unsigned*)&Wt[(n * 8 + g) * SA + k0 + tg * 2];
            unsigned b1 = *(const unsigned*)&Wt[(n * 8 + g) * SA + k0 + tg * 2 + 8];
            mma16816(c[n], a0, a1, a2, a3, b0, b1);
        }
    }
    int row0 = base + R + g;
    int row1 = row0 + 8;
    float dis0 = (row0 < N_NODES) ? g_dis[row0] : 0.0f;
    float dis1 = (row1 < N_NODES) ? g_dis[row1] : 0.0f;
    #pragma unroll
    for (int n = 0; n < 8; n++) {
        int col = n * 8 + tg * 2;
        if (row0 < N_NODES) {
            __half2 h = __floats2half2_rn(c[n][0] * dis0, c[n][1] * dis0);
            *(__half2*)&outbuf[row0 * F + col] = h;
        }
        if (row1 < N_NODES) {
            __half2 h = __floats2half2_rn(c[n][2] * dis1, c[n][3] * dis1);
            *(__half2*)&outbuf[row1 * F + col] = h;
        }
    }
}

// Load transposed weights into SA-strided smem. NT threads participating.
template<int NT>
__device__ __forceinline__ void load_Wt_smem(__half* Wt, const __half* Wg) {
    int t = threadIdx.x;
    #pragma unroll
    for (int j = 0; j < 512 / NT; j++) {
        int idx = t + NT * j;          // 512 uint4
        int n = idx >> 3, q = idx & 7;
        uint4 u = ((const uint4*)Wg)[idx];
        __half* p = &Wt[n * SA + q * 8];
        *(unsigned*)(p + 0) = u.x;
        *(unsigned*)(p + 2) = u.y;
        *(unsigned*)(p + 4) = u.z;
        *(unsigned*)(p + 6) = u.w;
    }
}

// ---------------- fused: bin (latency-bound) ∪ GEMM1 (DRAM/tensor-bound) -----
__global__ void k_binmm1(const int* __restrict__ edge, const float* __restrict__ x) {
    __shared__ __half As[64 * SA];
    __shared__ __half Wt[64 * SA];
    if (blockIdx.x < BIN_BLOCKS) {
        int t = blockIdx.x * 128 + threadIdx.x;
        if (t < N_EDGES / 8) {
            const int4* S = (const int4*)edge;
            const int4* D = (const int4*)(edge + N_EDGES);
            int4 s0 = S[2 * t], s1 = S[2 * t + 1];
            int4 d0 = D[2 * t], d1 = D[2 * t + 1];
            int p0 = atomicAdd(&g_fill[d0.x], 1);
            int p1 = atomicAdd(&g_fill[d0.y], 1);
            int p2 = atomicAdd(&g_fill[d0.z], 1);
            int p3 = atomicAdd(&g_fill[d0.w], 1);
            int p4 = atomicAdd(&g_fill[d1.x], 1);
            int p5 = atomicAdd(&g_fill[d1.y], 1);
            int p6 = atomicAdd(&g_fill[d1.z], 1);
            int p7 = atomicAdd(&g_fill[d1.w], 1);
            g_srcs[p0] = s0.x;
            g_srcs[p1] = s0.y;
            g_srcs[p2] = s0.z;
            g_srcs[p3] = s0.w;
            g_srcs[p4] = s1.x;
            g_srcs[p5] = s1.y;
            g_srcs[p6] = s1.z;
            g_srcs[p7] = s1.w;
        }
    } else {
        int t = threadIdx.x;
        int base = (blockIdx.x - BIN_BLOCKS) * 64;
        load_Wt_smem<128>(Wt, g_W1t);
        #pragma unroll
        for (int j = 0; j < 8; j++) {
            int idx = t + 128 * j;          // 1024 float4
            int r = idx >> 4, q = idx & 15;
            int row = base + r;
            float4 f = (row < N_NODES) ? ((const float4*)x)[(long long)row * 16 + q]
                                       : make_float4(0.f, 0.f, 0.f, 0.f);
            __half* p = &As[r * SA + q * 4];
            *(__half2*)(p + 0) = __floats2half2_rn(f.x, f.y);
            *(__half2*)(p + 2) = __floats2half2_rn(f.z, f.w);
        }
        __syncthreads();
        mma_body<64>(As, Wt, base, g_bufA);
    }
}

// ---------------- fused agg0 + GEMM2: 256 threads, 32 nodes/block ------------
// Phase 1 (all 256 threads): gather layer-1 sums from bufA, self-loop + bias +
// relu, h (fp16) -> SA-strided smem tile (32 rows).
// Phase 2 (warps 0-1): HMMA h @ W2t over 32 rows, scale by dis, xs2 -> bufH.
// No race: reads bufA, writes bufH.
__global__ __launch_bounds__(256) void k_agg0mm2(const float* __restrict__ b1) {
    __shared__ __half Hs[32 * SA];
    __shared__ __half Wt[64 * SA];
    int tid = threadIdx.x;
    int base = blockIdx.x * 32;
    load_Wt_smem<256>(Wt, g_W2t);
    int r = tid >> 3;                 // local node 0..31
    int lane = tid & 7;
    int node = base + r;
    float h[8] = {};
    if (node < N_NODES) {
        int beg = g_rowptr[node];
        int end = g_fill[node];
        float acc[8] = {};
        gather_sum(acc, beg, end, lane, g_bufA);
        float dis = g_dis[node];
        float xs[8] = {};
        acc_half8(xs, __ldg(&((const uint4*)g_bufA)[node * 8 + lane]));
        #pragma unroll
        for (int j = 0; j < 8; j++)
            h[j] = fmaxf(dis * (acc[j] + xs[j]) + b1[lane * 8 + j], 0.0f);
    }
    __half* p = &Hs[r * SA + lane * 8];
    #pragma unroll
    for (int j = 0; j < 4; j++)
        *(__half2*)(p + 2 * j) = __floats2half2_rn(h[2 * j], h[2 * j + 1]);
    __syncthreads();
    if (tid < 64) mma_body<32>(Hs, Wt, base, g_bufH);
}

// ---------------- agg1 (reads bufH) fused with relu + mean-pool ----------------
__global__ void k_agg1(const float* __restrict__ b2, const int* __restrict__ batch) {
    __shared__ float hacc[32 * F];
    int tid = threadIdx.x;
    int s = tid >> 3;
    int lane = tid & 7;
    int base = blockIdx.x * 32;
    int node = base + s;
    int beg = g_rowptr[node];
    int end = g_fill[node];
    float acc[8] = {};
    gather_sum(acc, beg, end, lane, g_bufH);
    float dis = g_dis[node];
    float xs[8] = {};
    acc_half8(xs, __ldg(&((const uint4*)g_bufH)[node * 8 + lane]));
    float h[8];
    #pragma unroll
    for (int j = 0; j < 8; j++)
        h[j] = fmaxf(dis * (acc[j] + xs[j]) + b2[lane * 8 + j], 0.0f);
    #pragma unroll
    for (int j = 0; j < 8; j++) hacc[s * F + lane * 8 + j] = h[j];
    __syncthreads();

    int g0 = batch[base];
    int g1 = batch[base + 31];
    if (g0 == g1) {
        #pragma unroll
        for (int off = 16; off >= 1; off >>= 1) {
            if (s < off) {
                #pragma unroll
                for (int j = 0; j < 8; j++)
                    hacc[s * F + lane * 8 + j] += hacc[(s + off) * F + lane * 8 + j];
            }
            __syncthreads();
        }
        if (tid < 16) {
            float4 v = ((float4*)hacc)[tid];
            red_v4(&g_gsum[g0 * F + tid * 4], v.x, v.y, v.z, v.w);
        }
    } else {
        int g = batch[node];
        red_v4(&g_gsum[g * F + lane * 8 + 0], h[0], h[1], h[2], h[3]);
        red_v4(&g_gsum[g * F + lane * 8 + 4], h[4], h[5], h[6], h[7]);
    }
}

// ---------------- head ----------------
__global__ void k_head(const float* __restrict__ topo, const float* __restrict__ Wlin,
                       const float* __restrict__ blin, float* __restrict__ out) {
    int t = threadIdx.x;
    int g = t >> 2, c = t & 3;
    float inv = 1.0f / fmaxf(g_gcnt[g], 1.0f);
    float acc = blin[c];
    #pragma unroll
    for (int k = 0; k < F; k++)
        acc = fmaf(g_gsum[g * F + k] * inv, Wlin[k * NUM_CLASSES + c], acc);
    #pragma unroll
    for (int k = 0; k < TOPO_DIM; k++)
        acc = fmaf(topo[g * TOPO_DIM + k], Wlin[(F + k) * NUM_CLASSES + c], acc);
    out[g * NUM_CLASSES + c] = acc;
}

extern "C" void kernel_launch(void* const* d_in, const int* in_sizes, int n_in,
                              void* d_out, int out_size) {
    const float* x    = (const float*)d_in[0];
    const int*   edge = (const int*)d_in[1];
    const int*   batch= (const int*)d_in[2];
    const float* topo = (const float*)d_in[3];
    const float* W1   = (const float*)d_in[4];
    const float* b1   = (const float*)d_in[5];
    const float* W2   = (const float*)d_in[6];
    const float* b2   = (const float*)d_in[7];
    const float* Wlin = (const float*)d_in[8];
    const float* blin = (const float*)d_in[9];
    float* out = (float*)d_out;

    const int a1blocks = (N_NODES + 31) / 32;         // 3125
    const int eblocks = (N_EDGES / 8 + 255) / 256;    // 782

    k_pre<<<eblocks, 256>>>(edge, W1, W2);
    k_scan<<<SCAN_NBLK, SCAN_BLK>>>(batch);
    k_binmm1<<<BIN_BLOCKS + G1_BLOCKS, 128>>>(edge, x);
    k_agg0mm2<<<a1blocks, 256>>>(b1);
    k_agg1<<<a1blocks, 256>>>(b2, batch);
    k_head<<<1, 256>>>(topo, Wlin, blin, out);
}